// round 1
// baseline (speedup 1.0000x reference)
#include <cuda_runtime.h>
#include <math.h>

// Problem constants
#define Bb 4
#define Tt 2048
#define Cc 1024
#define Hh 16
#define Dd 64
#define BT (Bb*Tt)          // 8192
#define C3 (3*Cc)           // 3072

// Scratch (no cudaMalloc allowed)
__device__ float g_qkv[BT * C3];   // [8192, 3072]
__device__ float g_y[BT * Cc];     // [8192, 1024] attention output

// ---------------------------------------------------------------------------
// Classic register-tiled SGEMM with bias: C = A[MxK] * B[KxN] + bias[N]
// BM=128, BN=128, BK=8, TM=TN=8, 256 threads. All dims divisible, no bounds.
// ---------------------------------------------------------------------------
__global__ __launch_bounds__(256) void sgemm_bias(
    int M, int N, int K,
    const float* __restrict__ A, const float* __restrict__ Bm,
    const float* __restrict__ bias, float* __restrict__ Cout)
{
    const int BM = 128, BN = 128, BK = 8, TM = 8, TN = 8;
    __shared__ float As[BK][BM];
    __shared__ float Bs[BK][BN];

    const int tid = threadIdx.x;
    const int ty = tid >> 4;          // 0..15
    const int tx = tid & 15;          // 0..15
    const int rowBase = blockIdx.y * BM;
    const int colBase = blockIdx.x * BN;

    const int aRow = tid >> 1;            // 0..127
    const int aCol = (tid & 1) * 4;       // 0 or 4
    const int bRow = tid >> 5;            // 0..7
    const int bCol = (tid & 31) * 4;      // 0..124

    float acc[TM][TN];
    #pragma unroll
    for (int i = 0; i < TM; i++)
        #pragma unroll
        for (int j = 0; j < TN; j++) acc[i][j] = 0.f;

    for (int k0 = 0; k0 < K; k0 += BK) {
        float4 a4 = *(const float4*)&A[(size_t)(rowBase + aRow) * K + k0 + aCol];
        As[aCol + 0][aRow] = a4.x;
        As[aCol + 1][aRow] = a4.y;
        As[aCol + 2][aRow] = a4.z;
        As[aCol + 3][aRow] = a4.w;
        *(float4*)&Bs[bRow][bCol] =
            *(const float4*)&Bm[(size_t)(k0 + bRow) * N + colBase + bCol];
        __syncthreads();

        #pragma unroll
        for (int k = 0; k < BK; k++) {
            float ar[TM], br[TN];
            *(float4*)&ar[0] = *(float4*)&As[k][ty * TM];
            *(float4*)&ar[4] = *(float4*)&As[k][ty * TM + 4];
            *(float4*)&br[0] = *(float4*)&Bs[k][tx * TN];
            *(float4*)&br[4] = *(float4*)&Bs[k][tx * TN + 4];
            #pragma unroll
            for (int i = 0; i < TM; i++)
                #pragma unroll
                for (int j = 0; j < TN; j++)
                    acc[i][j] += ar[i] * br[j];
        }
        __syncthreads();
    }

    const int row0 = rowBase + ty * TM;
    const int col0 = colBase + tx * TN;
    float4 bb0 = *(const float4*)&bias[col0];
    float4 bb1 = *(const float4*)&bias[col0 + 4];
    #pragma unroll
    for (int i = 0; i < TM; i++) {
        float* dst = &Cout[(size_t)(row0 + i) * N + col0];
        float4 o0, o1;
        o0.x = acc[i][0] + bb0.x; o0.y = acc[i][1] + bb0.y;
        o0.z = acc[i][2] + bb0.z; o0.w = acc[i][3] + bb0.w;
        o1.x = acc[i][4] + bb1.x; o1.y = acc[i][5] + bb1.y;
        o1.z = acc[i][6] + bb1.z; o1.w = acc[i][7] + bb1.w;
        *(float4*)dst = o0;
        *(float4*)(dst + 4) = o1;
    }
}

// ---------------------------------------------------------------------------
// In-place RoPE on Q and K sections of qkv [8192, 3072].
// One thread per (row, pair) where pair in [0, C/2): handles q and k pairs.
// ---------------------------------------------------------------------------
__global__ __launch_bounds__(256) void rope_kernel(float* __restrict__ qkv)
{
    int idx = blockIdx.x * blockDim.x + threadIdx.x;   // 0 .. 8192*512-1
    const int TOTAL = BT * (Cc / 2);
    if (idx >= TOTAL) return;
    int pair = idx & (Cc / 2 - 1);  // 0..511  (= h*32 + i)
    int row  = idx >> 9;            // 0..8191
    int t    = row & (Tt - 1);
    int i    = pair & 31;           // pair index within head (D/2 = 32)

    // theta = 10000^(-2i/64) = 2^(-i * log2(10000)/32)
    float freq = exp2f(-(float)i * 0.4152410118609203f);
    float ang = (float)t * freq;
    float s, c;
    sincosf(ang, &s, &c);

    float* qp = qkv + (size_t)row * C3 + 2 * pair;      // q section
    float* kp = qp + Cc;                                 // k section
    float q1 = qp[0], q2 = qp[1];
    qp[0] = q1 * c - q2 * s;
    qp[1] = q1 * s + q2 * c;
    float k1 = kp[0], k2 = kp[1];
    kp[0] = k1 * c - k2 * s;
    kp[1] = k1 * s + k2 * c;
}

// ---------------------------------------------------------------------------
// Causal flash attention. Br=Bc=64, 256 threads (16x16), 4x4 regs per thread.
// Reads Q/K/V in-place from qkv (strided rows), writes y in [B,T,C] layout.
// ---------------------------------------------------------------------------
#define LDSW (Dd + 4)   // 68, keeps float4 alignment (68*4 = 272 = 17*16)

__global__ __launch_bounds__(256) void flash_attn(
    const float* __restrict__ qkv, float* __restrict__ y)
{
    __shared__ float Qs[Dd][LDSW];   // Qs[d][i]  (transposed)
    __shared__ float Ks[Dd][LDSW];   // Ks[d][j]  (transposed)
    __shared__ float Vs[64][LDSW];   // Vs[j][n]  (natural)
    __shared__ float Ps[64][LDSW];   // Ps[j][i]  (transposed P)

    const int bh = blockIdx.y;
    const int b = bh >> 4, h = bh & 15;
    const int qt = blockIdx.x;
    const int tid = threadIdx.x;
    const int ty = tid >> 4, tx = tid & 15;

    const float* qbase = qkv + (size_t)b * Tt * C3 + h * Dd;
    const float* kbase = qbase + Cc;
    const float* vbase = qbase + 2 * Cc;
    const int q0 = qt * 64;

    // Load Q tile transposed
    {
        int i = tid >> 2;
        const float* src = qbase + (size_t)(q0 + i) * C3;
        #pragma unroll
        for (int r = 0; r < 4; r++) {
            int d0 = ((tid & 3) * 4 + r) * 4;
            float4 v4 = *(const float4*)(src + d0);
            Qs[d0 + 0][i] = v4.x;
            Qs[d0 + 1][i] = v4.y;
            Qs[d0 + 2][i] = v4.z;
            Qs[d0 + 3][i] = v4.w;
        }
    }

    float acc[4][4];
    float mrow[4], lrow[4];
    #pragma unroll
    for (int i = 0; i < 4; i++) {
        mrow[i] = -1e30f; lrow[i] = 0.f;
        #pragma unroll
        for (int j = 0; j < 4; j++) acc[i][j] = 0.f;
    }

    for (int kt = 0; kt <= qt; kt++) {
        __syncthreads();   // previous iter's compute done (Q load on first)
        // Load K transposed + V natural
        {
            int j = tid >> 2;
            const float* ksrc = kbase + (size_t)(kt * 64 + j) * C3;
            const float* vsrc = vbase + (size_t)(kt * 64 + j) * C3;
            #pragma unroll
            for (int r = 0; r < 4; r++) {
                int d0 = ((tid & 3) * 4 + r) * 4;
                float4 kv = *(const float4*)(ksrc + d0);
                Ks[d0 + 0][j] = kv.x;
                Ks[d0 + 1][j] = kv.y;
                Ks[d0 + 2][j] = kv.z;
                Ks[d0 + 3][j] = kv.w;
                *(float4*)&Vs[j][d0] = *(const float4*)(vsrc + d0);
            }
        }
        __syncthreads();

        // S = Q K^T (4x4 per thread)
        float s[4][4];
        #pragma unroll
        for (int i = 0; i < 4; i++)
            #pragma unroll
            for (int j = 0; j < 4; j++) s[i][j] = 0.f;
        #pragma unroll
        for (int d = 0; d < Dd; d++) {
            float4 a4 = *(const float4*)&Qs[d][ty * 4];
            float4 b4 = *(const float4*)&Ks[d][tx * 4];
            float ar[4] = {a4.x, a4.y, a4.z, a4.w};
            float br[4] = {b4.x, b4.y, b4.z, b4.w};
            #pragma unroll
            for (int i = 0; i < 4; i++)
                #pragma unroll
                for (int j = 0; j < 4; j++)
                    s[i][j] += ar[i] * br[j];
        }

        const float scale = 0.125f;   // 1/sqrt(64)
        const bool diag = (kt == qt);
        #pragma unroll
        for (int i = 0; i < 4; i++)
            #pragma unroll
            for (int j = 0; j < 4; j++) {
                float sv = s[i][j] * scale;
                if (diag && (tx * 4 + j) > (ty * 4 + i)) sv = -1e30f;
                s[i][j] = sv;
            }

        // Online softmax update (row groups = 16 contiguous lanes)
        #pragma unroll
        for (int i = 0; i < 4; i++) {
            float mx = fmaxf(fmaxf(s[i][0], s[i][1]), fmaxf(s[i][2], s[i][3]));
            #pragma unroll
            for (int off = 8; off > 0; off >>= 1)
                mx = fmaxf(mx, __shfl_xor_sync(0xffffffffu, mx, off, 16));
            float mnew = fmaxf(mrow[i], mx);
            float alpha = __expf(mrow[i] - mnew);
            float sum = 0.f;
            #pragma unroll
            for (int j = 0; j < 4; j++) {
                float p = __expf(s[i][j] - mnew);
                s[i][j] = p;
                sum += p;
            }
            #pragma unroll
            for (int off = 8; off > 0; off >>= 1)
                sum += __shfl_xor_sync(0xffffffffu, sum, off, 16);
            lrow[i] = lrow[i] * alpha + sum;
            mrow[i] = mnew;
            #pragma unroll
            for (int j = 0; j < 4; j++) acc[i][j] *= alpha;
        }

        // Store P transposed: Ps[j][i]
        #pragma unroll
        for (int i = 0; i < 4; i++)
            #pragma unroll
            for (int j = 0; j < 4; j++)
                Ps[tx * 4 + j][ty * 4 + i] = s[i][j];
        __syncthreads();

        // O += P V
        #pragma unroll
        for (int j = 0; j < 64; j++) {
            float4 a4 = *(const float4*)&Ps[j][ty * 4];
            float4 b4 = *(const float4*)&Vs[j][tx * 4];
            float pr[4] = {a4.x, a4.y, a4.z, a4.w};
            float vr[4] = {b4.x, b4.y, b4.z, b4.w};
            #pragma unroll
            for (int i = 0; i < 4; i++)
                #pragma unroll
                for (int n = 0; n < 4; n++)
                    acc[i][n] += pr[i] * vr[n];
        }
    }

    // Epilogue: divide by l, write y[b][t][h*64 + n]
    #pragma unroll
    for (int i = 0; i < 4; i++) {
        float inv = 1.f / lrow[i];
        int t = q0 + ty * 4 + i;
        float* dst = y + ((size_t)b * Tt + t) * Cc + h * Dd + tx * 4;
        float4 o;
        o.x = acc[i][0] * inv;
        o.y = acc[i][1] * inv;
        o.z = acc[i][2] * inv;
        o.w = acc[i][3] * inv;
        *(float4*)dst = o;
    }
}

// ---------------------------------------------------------------------------
extern "C" void kernel_launch(void* const* d_in, const int* in_sizes, int n_in,
                              void* d_out, int out_size)
{
    const float* x      = (const float*)d_in[0];
    const float* W_qkv  = (const float*)d_in[1];
    const float* b_qkv  = (const float*)d_in[2];
    const float* W_proj = (const float*)d_in[3];
    const float* b_proj = (const float*)d_in[4];
    float* out = (float*)d_out;

    void* qkv_p = nullptr;
    void* y_p = nullptr;
    cudaGetSymbolAddress(&qkv_p, g_qkv);
    cudaGetSymbolAddress(&y_p, g_y);
    float* qkv = (float*)qkv_p;
    float* y = (float*)y_p;

    // 1) QKV GEMM: [8192,1024] @ [1024,3072] + b -> qkv
    {
        dim3 grid(C3 / 128, BT / 128);
        sgemm_bias<<<grid, 256>>>(BT, C3, Cc, x, W_qkv, b_qkv, qkv);
    }
    // 2) RoPE in-place on q,k
    {
        int total = BT * (Cc / 2);
        rope_kernel<<<(total + 255) / 256, 256>>>(qkv);
    }
    // 3) Flash attention
    {
        dim3 grid(Tt / 64, Bb * Hh);
        flash_attn<<<grid, 256>>>(qkv, y);
    }
    // 4) Output projection: [8192,1024] @ [1024,1024] + b -> out
    {
        dim3 grid(Cc / 128, BT / 128);
        sgemm_bias<<<grid, 256>>>(BT, Cc, Cc, y, W_proj, b_proj, out);
    }
}

// round 3
// speedup vs baseline: 1.5188x; 1.5188x over previous
#include <cuda_runtime.h>
#include <cuda_bf16.h>
#include <cstdint>
#include <math.h>

// Problem constants
#define Bb 4
#define Tt 2048
#define Cc 1024
#define Hh 16
#define Dd 64
#define BT (Bb*Tt)          // 8192
#define C3 (3*Cc)           // 3072

// ---------------------------------------------------------------------------
// Scratch (no cudaMalloc allowed)
// ---------------------------------------------------------------------------
__device__ float g_qkv[BT * C3];                 // [8192, 3072] fp32
__device__ float g_y[BT * Cc];                   // [8192, 1024] fp32
__device__ __nv_bfloat16 g_xhi[BT * Cc];         // x split
__device__ __nv_bfloat16 g_xlo[BT * Cc];
__device__ __nv_bfloat16 g_wq_hi[C3 * Cc];       // W_qkv^T split  [N=3072][K=1024]
__device__ __nv_bfloat16 g_wq_lo[C3 * Cc];
__device__ __nv_bfloat16 g_wp_hi[Cc * Cc];       // W_proj^T split [N=1024][K=1024]
__device__ __nv_bfloat16 g_wp_lo[Cc * Cc];
__device__ __nv_bfloat16 g_yhi[BT * Cc];         // y split
__device__ __nv_bfloat16 g_ylo[BT * Cc];

// ---------------------------------------------------------------------------
// Warp MMA helpers (plain sm_80+ features — no arch-suffix gating)
// ---------------------------------------------------------------------------
__device__ __forceinline__ uint32_t smem_to_u32(const void* p) {
    uint32_t a;
    asm("{ .reg .u64 t; cvta.to.shared.u64 t, %1; cvt.u32.u64 %0, t; }"
        : "=r"(a) : "l"(p));
    return a;
}
__device__ __forceinline__ void cp16(uint32_t d, const void* s) {
    asm volatile("cp.async.cg.shared.global [%0], [%1], 16;\n"
                 :: "r"(d), "l"(s) : "memory");
}
#define CP_COMMIT() asm volatile("cp.async.commit_group;" ::: "memory")
#define CP_WAIT(n)  asm volatile("cp.async.wait_group %0;" :: "n"(n) : "memory")

__device__ __forceinline__ void ldm_x4(uint32_t* r, uint32_t addr) {
    asm volatile("ldmatrix.sync.aligned.m8n8.x4.shared.b16 {%0,%1,%2,%3}, [%4];"
                 : "=r"(r[0]), "=r"(r[1]), "=r"(r[2]), "=r"(r[3]) : "r"(addr));
}
__device__ __forceinline__ void mma_bf16(float* d, const uint32_t* a,
                                         const uint32_t* b) {
    asm volatile(
        "mma.sync.aligned.m16n8k16.row.col.f32.bf16.bf16.f32 "
        "{%0,%1,%2,%3}, {%4,%5,%6,%7}, {%8,%9}, {%0,%1,%2,%3};"
        : "+f"(d[0]), "+f"(d[1]), "+f"(d[2]), "+f"(d[3])
        : "r"(a[0]), "r"(a[1]), "r"(a[2]), "r"(a[3]), "r"(b[0]), "r"(b[1]));
}

// ---------------------------------------------------------------------------
// Split-bf16 HMMA GEMM: C[M,N] = A[M,1024] * Bt[N,1024]^T + bias
// CTA tile 128x128, BK=32, 8 warps (4 in M x 2 in N), each warp 32x64.
// Double-buffered cp.async pipeline. A/B stored hi+lo, 3 MMA combos.
// ---------------------------------------------------------------------------
#define GPITCH 80                      // 32 bf16 (64B) + 16B pad, 16B aligned
#define GSEC   10240                   // 128 rows * 80B
#define GSTAGE (4 * GSEC)              // Ahi, Alo, Bhi, Blo
#define GEMM_SMEM (2 * GSTAGE)         // 81920

__global__ __launch_bounds__(256, 2) void gemm_mma(
    const __nv_bfloat16* __restrict__ Ahi, const __nv_bfloat16* __restrict__ Alo,
    const __nv_bfloat16* __restrict__ Bhi, const __nv_bfloat16* __restrict__ Blo,
    const float* __restrict__ bias, float* __restrict__ Cout, int N)
{
    extern __shared__ char sm[];
    const int tid = threadIdx.x, lane = tid & 31, wid = tid >> 5;
    const int warpM = wid >> 1, warpN = wid & 1;
    const int mBase = blockIdx.y * 128, nBase = blockIdx.x * 128;
    const uint32_t smBase = smem_to_u32(sm);

    // ldmatrix per-lane address pieces
    // A tiles: t=lane>>3: row += (t&1)*8, colByte = ((t>>1)&1)*16
    const int aoff = (warpM * 32 + (lane & 7) + ((lane >> 3) & 1) * 8) * GPITCH
                   + ((lane >> 4) & 1) * 16;
    // B tiles: t=lane>>3: row += (t>=2)*8, colByte = (t&1)*16
    const int boff = (warpN * 64 + (lane & 7) + ((lane >> 4) & 1) * 8) * GPITCH
                   + ((lane >> 3) & 1) * 16;

    float acc[2][8][4];
    #pragma unroll
    for (int a = 0; a < 2; a++)
        #pragma unroll
        for (int q = 0; q < 8; q++)
            #pragma unroll
            for (int v = 0; v < 4; v++) acc[a][q][v] = 0.f;

    auto ldChunk = [&](int c, int buf) {
        uint32_t base = smBase + buf * GSTAGE;
        const int k0 = c * 32;
        #pragma unroll
        for (int i = 0; i < 2; i++) {
            int idx = i * 256 + tid;
            int row = idx >> 2, s = idx & 3;
            uint32_t d = base + row * GPITCH + s * 16;
            size_t ga = (size_t)(mBase + row) * 1024 + k0 + s * 8;
            size_t gb = (size_t)(nBase + row) * 1024 + k0 + s * 8;
            cp16(d,            Ahi + ga);
            cp16(d + GSEC,     Alo + ga);
            cp16(d + 2 * GSEC, Bhi + gb);
            cp16(d + 3 * GSEC, Blo + gb);
        }
    };

    auto compute = [&](int buf) {
        uint32_t base = smBase + buf * GSTAGE;
        #pragma unroll
        for (int k16 = 0; k16 < 2; k16++) {
            uint32_t ah[2][4], al[2][4];
            #pragma unroll
            for (int a = 0; a < 2; a++) {
                uint32_t ad = base + aoff + a * (16 * GPITCH) + k16 * 32;
                ldm_x4(ah[a], ad);
                ldm_x4(al[a], ad + GSEC);
            }
            #pragma unroll
            for (int p = 0; p < 4; p++) {
                uint32_t bh[4], bl[4];
                uint32_t bd = base + 2 * GSEC + boff + p * (16 * GPITCH) + k16 * 32;
                ldm_x4(bh, bd);
                ldm_x4(bl, bd + GSEC);
                #pragma unroll
                for (int a = 0; a < 2; a++) {
                    mma_bf16(acc[a][p * 2 + 0], ah[a], bh);
                    mma_bf16(acc[a][p * 2 + 0], ah[a], bl);
                    mma_bf16(acc[a][p * 2 + 0], al[a], bh);
                    mma_bf16(acc[a][p * 2 + 1], ah[a], bh + 2);
                    mma_bf16(acc[a][p * 2 + 1], ah[a], bl + 2);
                    mma_bf16(acc[a][p * 2 + 1], al[a], bh + 2);
                }
            }
        }
    };

    ldChunk(0, 0);
    CP_COMMIT();
    #pragma unroll 1
    for (int c = 0; c < 32; c++) {
        const int buf = c & 1;
        if (c < 31) {
            ldChunk(c + 1, buf ^ 1);
            CP_COMMIT();
            CP_WAIT(1);
        } else {
            CP_WAIT(0);
        }
        __syncthreads();
        compute(buf);
        __syncthreads();
    }

    // Epilogue + bias
    const int r0 = mBase + warpM * 32 + (lane >> 2);
    #pragma unroll
    for (int a = 0; a < 2; a++)
        #pragma unroll
        for (int p = 0; p < 4; p++)
            #pragma unroll
            for (int h = 0; h < 2; h++) {
                int col = nBase + warpN * 64 + p * 16 + h * 8 + (lane & 3) * 2;
                float2 bb = *(const float2*)(bias + col);
                float* d0 = Cout + (size_t)(r0 + a * 16) * N + col;
                float2 o0 = { acc[a][p * 2 + h][0] + bb.x,
                              acc[a][p * 2 + h][1] + bb.y };
                *(float2*)d0 = o0;
                float* d1 = d0 + (size_t)8 * N;
                float2 o1 = { acc[a][p * 2 + h][2] + bb.x,
                              acc[a][p * 2 + h][3] + bb.y };
                *(float2*)d1 = o1;
            }
}

// ---------------------------------------------------------------------------
// fp32 -> (hi, lo) bf16 split
// ---------------------------------------------------------------------------
__global__ __launch_bounds__(256) void split_bf16(
    const float* __restrict__ x, __nv_bfloat16* __restrict__ hi,
    __nv_bfloat16* __restrict__ lo, int n4)
{
    int i = blockIdx.x * blockDim.x + threadIdx.x;
    if (i >= n4) return;
    float4 v = ((const float4*)x)[i];
    __nv_bfloat16 h0 = __float2bfloat16(v.x);
    __nv_bfloat16 h1 = __float2bfloat16(v.y);
    __nv_bfloat16 h2 = __float2bfloat16(v.z);
    __nv_bfloat16 h3 = __float2bfloat16(v.w);
    __nv_bfloat16 l0 = __float2bfloat16(v.x - __bfloat162float(h0));
    __nv_bfloat16 l1 = __float2bfloat16(v.y - __bfloat162float(h1));
    __nv_bfloat16 l2 = __float2bfloat16(v.z - __bfloat162float(h2));
    __nv_bfloat16 l3 = __float2bfloat16(v.w - __bfloat162float(h3));
    __nv_bfloat162* hp = (__nv_bfloat162*)(hi + i * 4);
    __nv_bfloat162* lp = (__nv_bfloat162*)(lo + i * 4);
    hp[0] = __nv_bfloat162(h0, h1); hp[1] = __nv_bfloat162(h2, h3);
    lp[0] = __nv_bfloat162(l0, l1); lp[1] = __nv_bfloat162(l2, l3);
}

// ---------------------------------------------------------------------------
// W [K, N] fp32 -> Wt hi/lo bf16 [N, K] (transpose + split)
// ---------------------------------------------------------------------------
__global__ __launch_bounds__(256) void transpose_split(
    const float* __restrict__ W, __nv_bfloat16* __restrict__ thi,
    __nv_bfloat16* __restrict__ tlo, int K, int N)
{
    __shared__ float t[32][33];
    const int k0 = blockIdx.y * 32, n0 = blockIdx.x * 32;
    const int x = threadIdx.x, y = threadIdx.y;   // block (32, 8)
    #pragma unroll
    for (int r = 0; r < 32; r += 8)
        t[y + r][x] = W[(size_t)(k0 + y + r) * N + n0 + x];
    __syncthreads();
    #pragma unroll
    for (int r = 0; r < 32; r += 8) {
        float v = t[x][y + r];                    // = W[k0+x][n0+y+r]
        __nv_bfloat16 h = __float2bfloat16(v);
        __nv_bfloat16 l = __float2bfloat16(v - __bfloat162float(h));
        size_t o = (size_t)(n0 + y + r) * K + k0 + x;
        thi[o] = h; tlo[o] = l;
    }
}

// ---------------------------------------------------------------------------
// In-place RoPE on Q and K sections of qkv [8192, 3072]
// ---------------------------------------------------------------------------
__global__ __launch_bounds__(256) void rope_kernel(float* __restrict__ qkv)
{
    int idx = blockIdx.x * blockDim.x + threadIdx.x;
    const int TOTAL = BT * (Cc / 2);
    if (idx >= TOTAL) return;
    int pair = idx & (Cc / 2 - 1);
    int row  = idx >> 9;
    int t    = row & (Tt - 1);
    int i    = pair & 31;

    float freq = exp2f(-(float)i * 0.4152410118609203f);
    float ang = (float)t * freq;
    float s, c;
    sincosf(ang, &s, &c);

    float* qp = qkv + (size_t)row * C3 + 2 * pair;
    float* kp = qp + Cc;
    float q1 = qp[0], q2 = qp[1];
    qp[0] = q1 * c - q2 * s;
    qp[1] = q1 * s + q2 * c;
    float k1 = kp[0], k2 = kp[1];
    kp[0] = k1 * c - k2 * s;
    kp[1] = k1 * s + k2 * c;
}

// ---------------------------------------------------------------------------
// Causal flash attention (fp32, unchanged — known good)
// ---------------------------------------------------------------------------
#define LDSW (Dd + 4)

__global__ __launch_bounds__(256) void flash_attn(
    const float* __restrict__ qkv, float* __restrict__ y)
{
    __shared__ float Qs[Dd][LDSW];
    __shared__ float Ks[Dd][LDSW];
    __shared__ float Vs[64][LDSW];
    __shared__ float Ps[64][LDSW];

    const int bh = blockIdx.y;
    const int b = bh >> 4, h = bh & 15;
    const int qt = blockIdx.x;
    const int tid = threadIdx.x;
    const int ty = tid >> 4, tx = tid & 15;

    const float* qbase = qkv + (size_t)b * Tt * C3 + h * Dd;
    const float* kbase = qbase + Cc;
    const float* vbase = qbase + 2 * Cc;
    const int q0 = qt * 64;

    {
        int i = tid >> 2;
        const float* src = qbase + (size_t)(q0 + i) * C3;
        #pragma unroll
        for (int r = 0; r < 4; r++) {
            int d0 = ((tid & 3) * 4 + r) * 4;
            float4 v4 = *(const float4*)(src + d0);
            Qs[d0 + 0][i] = v4.x;
            Qs[d0 + 1][i] = v4.y;
            Qs[d0 + 2][i] = v4.z;
            Qs[d0 + 3][i] = v4.w;
        }
    }

    float acc[4][4];
    float mrow[4], lrow[4];
    #pragma unroll
    for (int i = 0; i < 4; i++) {
        mrow[i] = -1e30f; lrow[i] = 0.f;
        #pragma unroll
        for (int j = 0; j < 4; j++) acc[i][j] = 0.f;
    }

    for (int kt = 0; kt <= qt; kt++) {
        __syncthreads();
        {
            int j = tid >> 2;
            const float* ksrc = kbase + (size_t)(kt * 64 + j) * C3;
            const float* vsrc = vbase + (size_t)(kt * 64 + j) * C3;
            #pragma unroll
            for (int r = 0; r < 4; r++) {
                int d0 = ((tid & 3) * 4 + r) * 4;
                float4 kv = *(const float4*)(ksrc + d0);
                Ks[d0 + 0][j] = kv.x;
                Ks[d0 + 1][j] = kv.y;
                Ks[d0 + 2][j] = kv.z;
                Ks[d0 + 3][j] = kv.w;
                *(float4*)&Vs[j][d0] = *(const float4*)(vsrc + d0);
            }
        }
        __syncthreads();

        float s[4][4];
        #pragma unroll
        for (int i = 0; i < 4; i++)
            #pragma unroll
            for (int j = 0; j < 4; j++) s[i][j] = 0.f;
        #pragma unroll
        for (int d = 0; d < Dd; d++) {
            float4 a4 = *(const float4*)&Qs[d][ty * 4];
            float4 b4 = *(const float4*)&Ks[d][tx * 4];
            float ar[4] = {a4.x, a4.y, a4.z, a4.w};
            float br[4] = {b4.x, b4.y, b4.z, b4.w};
            #pragma unroll
            for (int i = 0; i < 4; i++)
                #pragma unroll
                for (int j = 0; j < 4; j++)
                    s[i][j] += ar[i] * br[j];
        }

        const float scale = 0.125f;
        const bool diag = (kt == qt);
        #pragma unroll
        for (int i = 0; i < 4; i++)
            #pragma unroll
            for (int j = 0; j < 4; j++) {
                float sv = s[i][j] * scale;
                if (diag && (tx * 4 + j) > (ty * 4 + i)) sv = -1e30f;
                s[i][j] = sv;
            }

        #pragma unroll
        for (int i = 0; i < 4; i++) {
            float mx = fmaxf(fmaxf(s[i][0], s[i][1]), fmaxf(s[i][2], s[i][3]));
            #pragma unroll
            for (int off = 8; off > 0; off >>= 1)
                mx = fmaxf(mx, __shfl_xor_sync(0xffffffffu, mx, off, 16));
            float mnew = fmaxf(mrow[i], mx);
            float alpha = __expf(mrow[i] - mnew);
            float sum = 0.f;
            #pragma unroll
            for (int j = 0; j < 4; j++) {
                float p = __expf(s[i][j] - mnew);
                s[i][j] = p;
                sum += p;
            }
            #pragma unroll
            for (int off = 8; off > 0; off >>= 1)
                sum += __shfl_xor_sync(0xffffffffu, sum, off, 16);
            lrow[i] = lrow[i] * alpha + sum;
            mrow[i] = mnew;
            #pragma unroll
            for (int j = 0; j < 4; j++) acc[i][j] *= alpha;
        }

        #pragma unroll
        for (int i = 0; i < 4; i++)
            #pragma unroll
            for (int j = 0; j < 4; j++)
                Ps[tx * 4 + j][ty * 4 + i] = s[i][j];
        __syncthreads();

        #pragma unroll
        for (int j = 0; j < 64; j++) {
            float4 a4 = *(const float4*)&Ps[j][ty * 4];
            float4 b4 = *(const float4*)&Vs[j][tx * 4];
            float pr[4] = {a4.x, a4.y, a4.z, a4.w};
            float vr[4] = {b4.x, b4.y, b4.z, b4.w};
            #pragma unroll
            for (int i = 0; i < 4; i++)
                #pragma unroll
                for (int n = 0; n < 4; n++)
                    acc[i][n] += pr[i] * vr[n];
        }
    }

    #pragma unroll
    for (int i = 0; i < 4; i++) {
        float inv = 1.f / lrow[i];
        int t = q0 + ty * 4 + i;
        float* dst = y + ((size_t)b * Tt + t) * Cc + h * Dd + tx * 4;
        float4 o;
        o.x = acc[i][0] * inv;
        o.y = acc[i][1] * inv;
        o.z = acc[i][2] * inv;
        o.w = acc[i][3] * inv;
        *(float4*)dst = o;
    }
}

// ---------------------------------------------------------------------------
extern "C" void kernel_launch(void* const* d_in, const int* in_sizes, int n_in,
                              void* d_out, int out_size)
{
    const float* x      = (const float*)d_in[0];
    const float* W_qkv  = (const float*)d_in[1];
    const float* b_qkv  = (const float*)d_in[2];
    const float* W_proj = (const float*)d_in[3];
    const float* b_proj = (const float*)d_in[4];
    float* out = (float*)d_out;

    void *qkv_p, *y_p, *xh_p, *xl_p, *wqh_p, *wql_p, *wph_p, *wpl_p, *yh_p, *yl_p;
    cudaGetSymbolAddress(&qkv_p, g_qkv);
    cudaGetSymbolAddress(&y_p, g_y);
    cudaGetSymbolAddress(&xh_p, g_xhi);
    cudaGetSymbolAddress(&xl_p, g_xlo);
    cudaGetSymbolAddress(&wqh_p, g_wq_hi);
    cudaGetSymbolAddress(&wql_p, g_wq_lo);
    cudaGetSymbolAddress(&wph_p, g_wp_hi);
    cudaGetSymbolAddress(&wpl_p, g_wp_lo);
    cudaGetSymbolAddress(&yh_p, g_yhi);
    cudaGetSymbolAddress(&yl_p, g_ylo);
    float* qkv = (float*)qkv_p;
    float* y = (float*)y_p;

    cudaFuncSetAttribute(gemm_mma, cudaFuncAttributeMaxDynamicSharedMemorySize,
                         GEMM_SMEM);

    // 1) Split x -> bf16 hi/lo
    split_bf16<<<(BT * Cc / 4 + 255) / 256, 256>>>(
        x, (__nv_bfloat16*)xh_p, (__nv_bfloat16*)xl_p, BT * Cc / 4);
    // 2) Transpose+split weights
    {
        dim3 g(C3 / 32, Cc / 32);
        transpose_split<<<g, dim3(32, 8)>>>(W_qkv,
            (__nv_bfloat16*)wqh_p, (__nv_bfloat16*)wql_p, Cc, C3);
    }
    {
        dim3 g(Cc / 32, Cc / 32);
        transpose_split<<<g, dim3(32, 8)>>>(W_proj,
            (__nv_bfloat16*)wph_p, (__nv_bfloat16*)wpl_p, Cc, Cc);
    }
    // 3) QKV GEMM (HMMA): [8192,1024] x [1024,3072] + b -> qkv
    {
        dim3 grid(C3 / 128, BT / 128);
        gemm_mma<<<grid, 256, GEMM_SMEM>>>(
            (const __nv_bfloat16*)xh_p, (const __nv_bfloat16*)xl_p,
            (const __nv_bfloat16*)wqh_p, (const __nv_bfloat16*)wql_p,
            b_qkv, qkv, C3);
    }
    // 4) RoPE
    {
        int total = BT * (Cc / 2);
        rope_kernel<<<(total + 255) / 256, 256>>>(qkv);
    }
    // 5) Flash attention
    {
        dim3 grid(Tt / 64, Bb * Hh);
        flash_attn<<<grid, 256>>>(qkv, y);
    }
    // 6) Split y
    split_bf16<<<(BT * Cc / 4 + 255) / 256, 256>>>(
        y, (__nv_bfloat16*)yh_p, (__nv_bfloat16*)yl_p, BT * Cc / 4);
    // 7) Output projection (HMMA): [8192,1024] x [1024,1024] + b -> out
    {
        dim3 grid(Cc / 128, BT / 128);
        gemm_mma<<<grid, 256, GEMM_SMEM>>>(
            (const __nv_bfloat16*)yh_p, (const __nv_bfloat16*)yl_p,
            (const __nv_bfloat16*)wph_p, (const __nv_bfloat16*)wpl_p,
            b_proj, out, Cc);
    }
}

// round 4
// speedup vs baseline: 2.8839x; 1.8988x over previous
#include <cuda_runtime.h>
#include <cuda_bf16.h>
#include <cstdint>
#include <math.h>

// Problem constants
#define Bb 4
#define Tt 2048
#define Cc 1024
#define Hh 16
#define Dd 64
#define BT (Bb*Tt)          // 8192
#define C3 (3*Cc)           // 3072

// ---------------------------------------------------------------------------
// Scratch (no cudaMalloc allowed)
// ---------------------------------------------------------------------------
__device__ float g_qkv[BT * C3];                 // [8192, 3072] fp32
__device__ __nv_bfloat16 g_qkvh[BT * C3];        // roped qkv hi
__device__ __nv_bfloat16 g_qkvl[BT * C3];        // roped qkv lo
__device__ __nv_bfloat16 g_xhi[BT * Cc];         // x split
__device__ __nv_bfloat16 g_xlo[BT * Cc];
__device__ __nv_bfloat16 g_wq_hi[C3 * Cc];       // W_qkv^T split  [N=3072][K=1024]
__device__ __nv_bfloat16 g_wq_lo[C3 * Cc];
__device__ __nv_bfloat16 g_wp_hi[Cc * Cc];       // W_proj^T split [N=1024][K=1024]
__device__ __nv_bfloat16 g_wp_lo[Cc * Cc];
__device__ __nv_bfloat16 g_yhi[BT * Cc];         // attention out split
__device__ __nv_bfloat16 g_ylo[BT * Cc];

// ---------------------------------------------------------------------------
// Warp MMA helpers (plain sm_80+ features — no arch-suffix gating)
// ---------------------------------------------------------------------------
__device__ __forceinline__ uint32_t smem_to_u32(const void* p) {
    uint32_t a;
    asm("{ .reg .u64 t; cvta.to.shared.u64 t, %1; cvt.u32.u64 %0, t; }"
        : "=r"(a) : "l"(p));
    return a;
}
__device__ __forceinline__ void cp16(uint32_t d, const void* s) {
    asm volatile("cp.async.cg.shared.global [%0], [%1], 16;\n"
                 :: "r"(d), "l"(s) : "memory");
}
#define CP_COMMIT() asm volatile("cp.async.commit_group;" ::: "memory")
#define CP_WAIT(n)  asm volatile("cp.async.wait_group %0;" :: "n"(n) : "memory")

__device__ __forceinline__ void ldm_x4(uint32_t* r, uint32_t addr) {
    asm volatile("ldmatrix.sync.aligned.m8n8.x4.shared.b16 {%0,%1,%2,%3}, [%4];"
                 : "=r"(r[0]), "=r"(r[1]), "=r"(r[2]), "=r"(r[3]) : "r"(addr));
}
__device__ __forceinline__ void ldm_x4_t(uint32_t* r, uint32_t addr) {
    asm volatile("ldmatrix.sync.aligned.m8n8.x4.trans.shared.b16 {%0,%1,%2,%3}, [%4];"
                 : "=r"(r[0]), "=r"(r[1]), "=r"(r[2]), "=r"(r[3]) : "r"(addr));
}
__device__ __forceinline__ void mma_bf16(float* d, const uint32_t* a,
                                         const uint32_t* b) {
    asm volatile(
        "mma.sync.aligned.m16n8k16.row.col.f32.bf16.bf16.f32 "
        "{%0,%1,%2,%3}, {%4,%5,%6,%7}, {%8,%9}, {%0,%1,%2,%3};"
        : "+f"(d[0]), "+f"(d[1]), "+f"(d[2]), "+f"(d[3])
        : "r"(a[0]), "r"(a[1]), "r"(a[2]), "r"(a[3]), "r"(b[0]), "r"(b[1]));
}
// split two floats into packed bf16x2 hi + lo (residual)
__device__ __forceinline__ void split2(float a, float b, uint32_t& hi, uint32_t& lo) {
    __nv_bfloat16 ha = __float2bfloat16(a), hb = __float2bfloat16(b);
    __nv_bfloat16 la = __float2bfloat16(a - __bfloat162float(ha));
    __nv_bfloat16 lb = __float2bfloat16(b - __bfloat162float(hb));
    __nv_bfloat162 h2(ha, hb), l2(la, lb);
    hi = *(uint32_t*)&h2;
    lo = *(uint32_t*)&l2;
}

// ---------------------------------------------------------------------------
// Split-bf16 HMMA GEMM (unchanged from R3 — known good)
// ---------------------------------------------------------------------------
#define GPITCH 80
#define GSEC   10240
#define GSTAGE (4 * GSEC)
#define GEMM_SMEM (2 * GSTAGE)

__global__ __launch_bounds__(256, 2) void gemm_mma(
    const __nv_bfloat16* __restrict__ Ahi, const __nv_bfloat16* __restrict__ Alo,
    const __nv_bfloat16* __restrict__ Bhi, const __nv_bfloat16* __restrict__ Blo,
    const float* __restrict__ bias, float* __restrict__ Cout, int N)
{
    extern __shared__ char sm[];
    const int tid = threadIdx.x, lane = tid & 31, wid = tid >> 5;
    const int warpM = wid >> 1, warpN = wid & 1;
    const int mBase = blockIdx.y * 128, nBase = blockIdx.x * 128;
    const uint32_t smBase = smem_to_u32(sm);

    const int aoff = (warpM * 32 + (lane & 7) + ((lane >> 3) & 1) * 8) * GPITCH
                   + ((lane >> 4) & 1) * 16;
    const int boff = (warpN * 64 + (lane & 7) + ((lane >> 4) & 1) * 8) * GPITCH
                   + ((lane >> 3) & 1) * 16;

    float acc[2][8][4];
    #pragma unroll
    for (int a = 0; a < 2; a++)
        #pragma unroll
        for (int q = 0; q < 8; q++)
            #pragma unroll
            for (int v = 0; v < 4; v++) acc[a][q][v] = 0.f;

    auto ldChunk = [&](int c, int buf) {
        uint32_t base = smBase + buf * GSTAGE;
        const int k0 = c * 32;
        #pragma unroll
        for (int i = 0; i < 2; i++) {
            int idx = i * 256 + tid;
            int row = idx >> 2, s = idx & 3;
            uint32_t d = base + row * GPITCH + s * 16;
            size_t ga = (size_t)(mBase + row) * 1024 + k0 + s * 8;
            size_t gb = (size_t)(nBase + row) * 1024 + k0 + s * 8;
            cp16(d,            Ahi + ga);
            cp16(d + GSEC,     Alo + ga);
            cp16(d + 2 * GSEC, Bhi + gb);
            cp16(d + 3 * GSEC, Blo + gb);
        }
    };

    auto compute = [&](int buf) {
        uint32_t base = smBase + buf * GSTAGE;
        #pragma unroll
        for (int k16 = 0; k16 < 2; k16++) {
            uint32_t ah[2][4], al[2][4];
            #pragma unroll
            for (int a = 0; a < 2; a++) {
                uint32_t ad = base + aoff + a * (16 * GPITCH) + k16 * 32;
                ldm_x4(ah[a], ad);
                ldm_x4(al[a], ad + GSEC);
            }
            #pragma unroll
            for (int p = 0; p < 4; p++) {
                uint32_t bh[4], bl[4];
                uint32_t bd = base + 2 * GSEC + boff + p * (16 * GPITCH) + k16 * 32;
                ldm_x4(bh, bd);
                ldm_x4(bl, bd + GSEC);
                #pragma unroll
                for (int a = 0; a < 2; a++) {
                    mma_bf16(acc[a][p * 2 + 0], ah[a], bh);
                    mma_bf16(acc[a][p * 2 + 0], ah[a], bl);
                    mma_bf16(acc[a][p * 2 + 0], al[a], bh);
                    mma_bf16(acc[a][p * 2 + 1], ah[a], bh + 2);
                    mma_bf16(acc[a][p * 2 + 1], ah[a], bl + 2);
                    mma_bf16(acc[a][p * 2 + 1], al[a], bh + 2);
                }
            }
        }
    };

    ldChunk(0, 0);
    CP_COMMIT();
    #pragma unroll 1
    for (int c = 0; c < 32; c++) {
        const int buf = c & 1;
        if (c < 31) {
            ldChunk(c + 1, buf ^ 1);
            CP_COMMIT();
            CP_WAIT(1);
        } else {
            CP_WAIT(0);
        }
        __syncthreads();
        compute(buf);
        __syncthreads();
    }

    const int r0 = mBase + warpM * 32 + (lane >> 2);
    #pragma unroll
    for (int a = 0; a < 2; a++)
        #pragma unroll
        for (int p = 0; p < 4; p++)
            #pragma unroll
            for (int h = 0; h < 2; h++) {
                int col = nBase + warpN * 64 + p * 16 + h * 8 + (lane & 3) * 2;
                float2 bb = *(const float2*)(bias + col);
                float* d0 = Cout + (size_t)(r0 + a * 16) * N + col;
                float2 o0 = { acc[a][p * 2 + h][0] + bb.x,
                              acc[a][p * 2 + h][1] + bb.y };
                *(float2*)d0 = o0;
                float* d1 = d0 + (size_t)8 * N;
                float2 o1 = { acc[a][p * 2 + h][2] + bb.x,
                              acc[a][p * 2 + h][3] + bb.y };
                *(float2*)d1 = o1;
            }
}

// ---------------------------------------------------------------------------
// HMMA flash attention. Br=64 (4 warps x m16), Bc=64. Split-bf16 QK^T and PV.
// Q kept in registers; K/V double-buffered via cp.async.
// Writes y directly as bf16 hi/lo.
// ---------------------------------------------------------------------------
#define FP 144                     // smem pitch for 64 bf16 rows (9 x 16B)
#define FQSZ (64 * FP)             // 9216
#define FKV  (4 * FQSZ)            // one K/V stage: Kh,Kl,Vh,Vl
#define FLASH_SMEM (2 * FQSZ + 2 * FKV)   // 92160

__global__ __launch_bounds__(128) void flash_mma(
    const __nv_bfloat16* __restrict__ qh, const __nv_bfloat16* __restrict__ ql,
    __nv_bfloat16* __restrict__ yh, __nv_bfloat16* __restrict__ yl)
{
    extern __shared__ char sm[];
    const int tid = threadIdx.x, lane = tid & 31, wid = tid >> 5;
    const int bh = blockIdx.y, b = bh >> 4, h = bh & 15;
    const int qt = (gridDim.x - 1) - blockIdx.x;   // heavy CTAs first
    const int q0 = qt * 64;
    const size_t grow = (size_t)b * Tt;

    const uint32_t QH = smem_to_u32(sm);
    const uint32_t KV0 = QH + 2 * FQSZ;

    // prefetch Q (hi+lo) and K/V tile 0
    {
        #pragma unroll
        for (int i = 0; i < 4; i++) {
            int idx = i * 128 + tid;          // 0..511
            int row = idx >> 3, ch = idx & 7;
            uint32_t d = QH + row * FP + ch * 16;
            size_t src = (grow + q0 + row) * C3 + h * Dd + ch * 8;
            cp16(d,        qh + src);
            cp16(d + FQSZ, ql + src);
        }
    }
    auto prefetchKV = [&](int kt, int buf) {
        uint32_t base = KV0 + buf * FKV;
        #pragma unroll
        for (int i = 0; i < 4; i++) {
            int idx = i * 128 + tid;
            int row = idx >> 3, ch = idx & 7;
            uint32_t d = base + row * FP + ch * 16;
            size_t srcK = (grow + kt * 64 + row) * C3 + Cc + h * Dd + ch * 8;
            size_t srcV = srcK + Cc;
            cp16(d,            qh + srcK);
            cp16(d + FQSZ,     ql + srcK);
            cp16(d + 2 * FQSZ, qh + srcV);
            cp16(d + 3 * FQSZ, ql + srcV);
        }
    };
    prefetchKV(0, 0);
    CP_COMMIT();
    CP_WAIT(0);
    __syncthreads();

    // Q fragments (held in regs for the whole kernel)
    uint32_t qhf[4][4], qlf[4][4];
    {
        uint32_t a = QH + (wid * 16 + (lane & 15)) * FP + ((lane >> 4) & 1) * 16;
        #pragma unroll
        for (int k16 = 0; k16 < 4; k16++) {
            ldm_x4(qhf[k16], a + k16 * 32);
            ldm_x4(qlf[k16], a + FQSZ + k16 * 32);
        }
    }

    float o[8][4];
    float mrow[2] = {-1e30f, -1e30f}, lrow[2] = {0.f, 0.f};
    #pragma unroll
    for (int d = 0; d < 8; d++)
        #pragma unroll
        for (int v = 0; v < 4; v++) o[d][v] = 0.f;

    #pragma unroll 1
    for (int kt = 0; kt <= qt; kt++) {
        const int buf = kt & 1;
        if (kt > 0) { CP_WAIT(0); __syncthreads(); }
        if (kt < qt) { prefetchKV(kt + 1, buf ^ 1); CP_COMMIT(); }

        const uint32_t KB = KV0 + buf * FKV;

        // ---- S = Q K^T (split) ----
        float s[8][4];
        #pragma unroll
        for (int n = 0; n < 8; n++)
            #pragma unroll
            for (int v = 0; v < 4; v++) s[n][v] = 0.f;

        #pragma unroll
        for (int k16 = 0; k16 < 4; k16++) {
            #pragma unroll
            for (int np = 0; np < 4; np++) {
                uint32_t kh4[4], kl4[4];
                uint32_t ad = KB + (np * 16 + (lane & 7) + ((lane >> 4) & 1) * 8) * FP
                            + ((lane >> 3) & 1) * 16 + k16 * 32;
                ldm_x4(kh4, ad);
                ldm_x4(kl4, ad + FQSZ);
                mma_bf16(s[2 * np],     qhf[k16], kh4);
                mma_bf16(s[2 * np],     qhf[k16], kl4);
                mma_bf16(s[2 * np],     qlf[k16], kh4);
                mma_bf16(s[2 * np + 1], qhf[k16], kh4 + 2);
                mma_bf16(s[2 * np + 1], qhf[k16], kl4 + 2);
                mma_bf16(s[2 * np + 1], qlf[k16], kh4 + 2);
            }
        }

        // ---- scale + causal mask ----
        #pragma unroll
        for (int n = 0; n < 8; n++)
            #pragma unroll
            for (int v = 0; v < 4; v++) s[n][v] *= 0.125f;
        if (kt == qt) {
            const int row0 = wid * 16 + (lane >> 2);
            #pragma unroll
            for (int n = 0; n < 8; n++) {
                int cb = n * 8 + (lane & 3) * 2;
                #pragma unroll
                for (int r = 0; r < 2; r++)
                    #pragma unroll
                    for (int j = 0; j < 2; j++)
                        if (cb + j > row0 + r * 8) s[n][2 * r + j] = -1e30f;
            }
        }

        // ---- online softmax (2 rows per thread) ----
        #pragma unroll
        for (int r = 0; r < 2; r++) {
            float mx = -1e30f;
            #pragma unroll
            for (int n = 0; n < 8; n++)
                mx = fmaxf(mx, fmaxf(s[n][2 * r], s[n][2 * r + 1]));
            mx = fmaxf(mx, __shfl_xor_sync(0xffffffffu, mx, 1));
            mx = fmaxf(mx, __shfl_xor_sync(0xffffffffu, mx, 2));
            float mnew = fmaxf(mrow[r], mx);
            float alpha = __expf(mrow[r] - mnew);
            float sum = 0.f;
            #pragma unroll
            for (int n = 0; n < 8; n++) {
                float p0 = __expf(s[n][2 * r] - mnew);
                float p1 = __expf(s[n][2 * r + 1] - mnew);
                s[n][2 * r] = p0; s[n][2 * r + 1] = p1;
                sum += p0 + p1;
            }
            sum += __shfl_xor_sync(0xffffffffu, sum, 1);
            sum += __shfl_xor_sync(0xffffffffu, sum, 2);
            lrow[r] = lrow[r] * alpha + sum;
            mrow[r] = mnew;
            #pragma unroll
            for (int d = 0; d < 8; d++) {
                o[d][2 * r] *= alpha;
                o[d][2 * r + 1] *= alpha;
            }
        }

        // ---- O += P V (split P in registers, V via ldmatrix.trans) ----
        #pragma unroll
        for (int k16 = 0; k16 < 4; k16++) {
            uint32_t phi[4], plo[4];
            const int t0 = 2 * k16, t1 = t0 + 1;
            split2(s[t0][0], s[t0][1], phi[0], plo[0]);
            split2(s[t0][2], s[t0][3], phi[1], plo[1]);
            split2(s[t1][0], s[t1][1], phi[2], plo[2]);
            split2(s[t1][2], s[t1][3], phi[3], plo[3]);
            #pragma unroll
            for (int dp = 0; dp < 4; dp++) {
                uint32_t vh4[4], vl4[4];
                uint32_t ad = KB + 2 * FQSZ
                            + (k16 * 16 + (lane & 7) + ((lane >> 3) & 1) * 8) * FP
                            + ((lane >> 4) & 1) * 16 + dp * 32;
                ldm_x4_t(vh4, ad);
                ldm_x4_t(vl4, ad + FQSZ);
                mma_bf16(o[2 * dp],     phi, vh4);
                mma_bf16(o[2 * dp],     phi, vl4);
                mma_bf16(o[2 * dp],     plo, vh4);
                mma_bf16(o[2 * dp + 1], phi, vh4 + 2);
                mma_bf16(o[2 * dp + 1], phi, vl4 + 2);
                mma_bf16(o[2 * dp + 1], plo, vh4 + 2);
            }
        }
    }

    // ---- epilogue: normalize, split to bf16 hi/lo, store ----
    #pragma unroll
    for (int r = 0; r < 2; r++) {
        const int t = q0 + wid * 16 + (lane >> 2) + r * 8;
        const float inv = 1.f / lrow[r];
        const size_t ro = (grow + t) * Cc + h * Dd;
        #pragma unroll
        for (int d = 0; d < 8; d++) {
            int col = d * 8 + (lane & 3) * 2;
            float v0 = o[d][2 * r] * inv;
            float v1 = o[d][2 * r + 1] * inv;
            uint32_t hi, lo;
            split2(v0, v1, hi, lo);
            *(uint32_t*)(yh + ro + col) = hi;
            *(uint32_t*)(yl + ro + col) = lo;
        }
    }
}

// ---------------------------------------------------------------------------
// fp32 -> (hi, lo) bf16 split
// ---------------------------------------------------------------------------
__global__ __launch_bounds__(256) void split_bf16(
    const float* __restrict__ x, __nv_bfloat16* __restrict__ hi,
    __nv_bfloat16* __restrict__ lo, int n4)
{
    int i = blockIdx.x * blockDim.x + threadIdx.x;
    if (i >= n4) return;
    float4 v = ((const float4*)x)[i];
    __nv_bfloat16 h0 = __float2bfloat16(v.x);
    __nv_bfloat16 h1 = __float2bfloat16(v.y);
    __nv_bfloat16 h2 = __float2bfloat16(v.z);
    __nv_bfloat16 h3 = __float2bfloat16(v.w);
    __nv_bfloat16 l0 = __float2bfloat16(v.x - __bfloat162float(h0));
    __nv_bfloat16 l1 = __float2bfloat16(v.y - __bfloat162float(h1));
    __nv_bfloat16 l2 = __float2bfloat16(v.z - __bfloat162float(h2));
    __nv_bfloat16 l3 = __float2bfloat16(v.w - __bfloat162float(h3));
    __nv_bfloat162* hp = (__nv_bfloat162*)(hi + i * 4);
    __nv_bfloat162* lp = (__nv_bfloat162*)(lo + i * 4);
    hp[0] = __nv_bfloat162(h0, h1); hp[1] = __nv_bfloat162(h2, h3);
    lp[0] = __nv_bfloat162(l0, l1); lp[1] = __nv_bfloat162(l2, l3);
}

// ---------------------------------------------------------------------------
// W [K, N] fp32 -> Wt hi/lo bf16 [N, K] (transpose + split)
// ---------------------------------------------------------------------------
__global__ __launch_bounds__(256) void transpose_split(
    const float* __restrict__ W, __nv_bfloat16* __restrict__ thi,
    __nv_bfloat16* __restrict__ tlo, int K, int N)
{
    __shared__ float t[32][33];
    const int k0 = blockIdx.y * 32, n0 = blockIdx.x * 32;
    const int x = threadIdx.x, y = threadIdx.y;   // block (32, 8)
    #pragma unroll
    for (int r = 0; r < 32; r += 8)
        t[y + r][x] = W[(size_t)(k0 + y + r) * N + n0 + x];
    __syncthreads();
    #pragma unroll
    for (int r = 0; r < 32; r += 8) {
        float v = t[x][y + r];
        __nv_bfloat16 h = __float2bfloat16(v);
        __nv_bfloat16 l = __float2bfloat16(v - __bfloat162float(h));
        size_t o = (size_t)(n0 + y + r) * K + k0 + x;
        thi[o] = h; tlo[o] = l;
    }
}

// ---------------------------------------------------------------------------
// RoPE on q,k + split whole qkv to bf16 hi/lo.
// grid (1536/256, 8192); each thread handles one (row, pair).
// ---------------------------------------------------------------------------
__global__ __launch_bounds__(256) void rope_split(
    const float* __restrict__ qkv,
    __nv_bfloat16* __restrict__ oh, __nv_bfloat16* __restrict__ ol)
{
    const int pc = blockIdx.x * 256 + threadIdx.x;   // 0..1535 pair index
    const int row = blockIdx.y;
    float2 v = *(const float2*)(qkv + (size_t)row * C3 + 2 * pc);

    if (pc < 1024) {      // q or k region: rotate
        int i = pc & 31;
        int t = row & (Tt - 1);
        float freq = exp2f(-(float)i * 0.4152410118609203f);
        float ang = (float)t * freq;
        float sn, cs;
        sincosf(ang, &sn, &cs);
        float a = v.x * cs - v.y * sn;
        float b = v.x * sn + v.y * cs;
        v.x = a; v.y = b;
    }
    uint32_t hi, lo;
    split2(v.x, v.y, hi, lo);
    size_t off = (size_t)row * C3 + 2 * pc;
    *(uint32_t*)(oh + off) = hi;
    *(uint32_t*)(ol + off) = lo;
}

// ---------------------------------------------------------------------------
extern "C" void kernel_launch(void* const* d_in, const int* in_sizes, int n_in,
                              void* d_out, int out_size)
{
    const float* x      = (const float*)d_in[0];
    const float* W_qkv  = (const float*)d_in[1];
    const float* b_qkv  = (const float*)d_in[2];
    const float* W_proj = (const float*)d_in[3];
    const float* b_proj = (const float*)d_in[4];
    float* out = (float*)d_out;

    void *qkv_p, *qh_p, *ql_p, *xh_p, *xl_p, *wqh_p, *wql_p, *wph_p, *wpl_p,
         *yh_p, *yl_p;
    cudaGetSymbolAddress(&qkv_p, g_qkv);
    cudaGetSymbolAddress(&qh_p, g_qkvh);
    cudaGetSymbolAddress(&ql_p, g_qkvl);
    cudaGetSymbolAddress(&xh_p, g_xhi);
    cudaGetSymbolAddress(&xl_p, g_xlo);
    cudaGetSymbolAddress(&wqh_p, g_wq_hi);
    cudaGetSymbolAddress(&wql_p, g_wq_lo);
    cudaGetSymbolAddress(&wph_p, g_wp_hi);
    cudaGetSymbolAddress(&wpl_p, g_wp_lo);
    cudaGetSymbolAddress(&yh_p, g_yhi);
    cudaGetSymbolAddress(&yl_p, g_ylo);
    float* qkv = (float*)qkv_p;

    cudaFuncSetAttribute(gemm_mma, cudaFuncAttributeMaxDynamicSharedMemorySize,
                         GEMM_SMEM);
    cudaFuncSetAttribute(flash_mma, cudaFuncAttributeMaxDynamicSharedMemorySize,
                         FLASH_SMEM);

    // 1) Split x -> bf16 hi/lo
    split_bf16<<<(BT * Cc / 4 + 255) / 256, 256>>>(
        x, (__nv_bfloat16*)xh_p, (__nv_bfloat16*)xl_p, BT * Cc / 4);
    // 2) Transpose+split weights
    {
        dim3 g(C3 / 32, Cc / 32);
        transpose_split<<<g, dim3(32, 8)>>>(W_qkv,
            (__nv_bfloat16*)wqh_p, (__nv_bfloat16*)wql_p, Cc, C3);
    }
    {
        dim3 g(Cc / 32, Cc / 32);
        transpose_split<<<g, dim3(32, 8)>>>(W_proj,
            (__nv_bfloat16*)wph_p, (__nv_bfloat16*)wpl_p, Cc, Cc);
    }
    // 3) QKV GEMM (HMMA): [8192,1024] x [1024,3072] + b -> qkv fp32
    {
        dim3 grid(C3 / 128, BT / 128);
        gemm_mma<<<grid, 256, GEMM_SMEM>>>(
            (const __nv_bfloat16*)xh_p, (const __nv_bfloat16*)xl_p,
            (const __nv_bfloat16*)wqh_p, (const __nv_bfloat16*)wql_p,
            b_qkv, qkv, C3);
    }
    // 4) RoPE + split to bf16 hi/lo
    {
        dim3 grid(C3 / 2 / 256, BT);
        rope_split<<<grid, 256>>>(qkv,
            (__nv_bfloat16*)qh_p, (__nv_bfloat16*)ql_p);
    }
    // 5) HMMA flash attention -> y hi/lo bf16
    {
        dim3 grid(Tt / 64, Bb * Hh);
        flash_mma<<<grid, 128, FLASH_SMEM>>>(
            (const __nv_bfloat16*)qh_p, (const __nv_bfloat16*)ql_p,
            (__nv_bfloat16*)yh_p, (__nv_bfloat16*)yl_p);
    }
    // 6) Output projection (HMMA): [8192,1024] x [1024,1024] + b -> out
    {
        dim3 grid(Cc / 128, BT / 128);
        gemm_mma<<<grid, 256, GEMM_SMEM>>>(
            (const __nv_bfloat16*)yh_p, (const __nv_bfloat16*)yl_p,
            (const __nv_bfloat16*)wph_p, (const __nv_bfloat16*)wpl_p,
            b_proj, out, Cc);
    }
}